// round 15
// baseline (speedup 1.0000x reference)
#include <cuda_runtime.h>
#include <cuda_fp16.h>
#include <math.h>
#include <stdint.h>

#define BB_ 32
#define T_ 128
#define D_ 128
#define H_ 132
#define O_ 64

#define NSTRIDE 24                    // fp16 per n-row (48B): [16 k-vals][8B pad] -> ldmatrix conflict-free
#define WCH_AB (144 * 48)             // 6912 B per k-step chunk (N=144)
#define WCH_C  (64 * 48)              // 3072 B per k-step chunk (N=64)
#define WBYTES_A (8 * WCH_AB)         // 55296
#define WBYTES_B (9 * WCH_AB)         // 62208
#define WBYTES_C (9 * WCH_C)          // 27648

// ---------------- main-kernel SMEM layout ----------------
#define OFF_X   0                     // 9 ksteps x 128 rows x 32B = 36864
#define OFF_W   36864                 // whole-stage weights, max 62208 -> 99072
#define OFF_B2  99072                 // 144 floats -> 99648
#define OFF_B3  99648                 // 64 floats  -> 99904
#define SMEM_TOTAL 99904              // x2 blocks = 199808 < 228KB/SM

// ---------------- PW-kernel SMEM layout (1-pass: X hi only) ----------------
#define PWK_W   32768                 // X (32768) then W (55296) -> 88064
#define PWK_B1  88064                 // 144 floats -> 88640
#define PWK_SMEM 88640                // x2 blocks = 177280

#define NBLK 2112                     // sum_t ceil((128-t)/4)

// ---------------- device scratch ----------------
__device__ float g_B4[4 * 32 * BB_ * D_];      // [p][j][bb][d]: max P over s in [4j+p, 4j+4+p)
__device__ float g_pre4[T_ * 32 * BB_ * D_];   // [t][ci][bb][d]: max over [t, t+4(ci+1))
__device__ float g_PW[T_ * BB_ * 144];         // [s][bb][n]: P(s,bb)·W1[128:256] + b1
__device__ __half g_W1h[8 * 144 * NSTRIDE];    // [kstep][n][24], W1 rows 0..127 (M part), fp16
__device__ __half g_W1pw[8 * 144 * NSTRIDE];   // [kstep][n][24], W1 rows 128..255 (P part), fp16
__device__ __half g_W2h[9 * 144 * NSTRIDE];
__device__ __half g_W3h[9 * 64 * NSTRIDE];
__device__ int g_map[NBLK];                    // packed (t<<8)|c

// ---------------- asm helpers ----------------
__device__ __forceinline__ void mma_f16(float d[4], const uint32_t a[4], const uint32_t b[2]) {
    asm volatile("mma.sync.aligned.m16n8k16.row.col.f32.f16.f16.f32 "
                 "{%0,%1,%2,%3}, {%4,%5,%6,%7}, {%8,%9}, {%0,%1,%2,%3};"
                 : "+f"(d[0]), "+f"(d[1]), "+f"(d[2]), "+f"(d[3])
                 : "r"(a[0]), "r"(a[1]), "r"(a[2]), "r"(a[3]), "r"(b[0]), "r"(b[1]));
}
__device__ __forceinline__ uint32_t smem_u32(const void* p) {
    uint32_t a;
    asm("{ .reg .u64 t; cvta.to.shared.u64 t, %1; cvt.u32.u64 %0, t; }" : "=r"(a) : "l"(p));
    return a;
}
#define CP16(dst, src) asm volatile("cp.async.ca.shared.global [%0], [%1], 16;" :: "r"(dst), "l"(src) : "memory")
#define CP_COMMIT()    asm volatile("cp.async.commit_group;" ::: "memory")
#define CP_WAIT0()     asm volatile("cp.async.wait_group 0;" ::: "memory")
#define LDSM4(r, a) asm volatile("ldmatrix.sync.aligned.m8n8.x4.shared.b16 {%0,%1,%2,%3}, [%4];" \
    : "=r"((r)[0]), "=r"((r)[1]), "=r"((r)[2]), "=r"((r)[3]) : "r"(a))
#define LDSM2(r, a) asm volatile("ldmatrix.sync.aligned.m8n8.x2.shared.b16 {%0,%1}, [%2];" \
    : "=r"((r)[0]), "=r"((r)[1]) : "r"(a))

// X element address with 16B-half swizzle (ldmatrix conflict-free); 128 rows/kstep
__device__ __forceinline__ int x_off(int ks, int row, int kk) {
    int phys = (kk >> 3) ^ ((row >> 2) & 1);
    return ks * 4096 + row * 32 + phys * 16 + (kk & 7) * 2;
}

// ---------------- prep: weights + tile map + phase-blocked 4-maxes + out init ----------------
__global__ void prep_all(const float* __restrict__ W1, const float* __restrict__ W2,
                         const float* __restrict__ W3, const float* __restrict__ P,
                         float* __restrict__ out) {
    int i = blockIdx.x * blockDim.x + threadIdx.x;
    if (blockIdx.x == 0 && threadIdx.x < 128) {
        int t = threadIdx.x;
        int start = 0;
        for (int u = 0; u < t; ++u) start += (131 - u) >> 2;
        int nch = (131 - t) >> 2;
        for (int c2 = 0; c2 < nch; ++c2) g_map[start + c2] = (t << 8) | c2;
    }
    if (i < 8 * 144 * NSTRIDE) {
        int ks = i / (144 * NSTRIDE), r = i % (144 * NSTRIDE);
        int n = r / NSTRIDE, kk = r % NSTRIDE;
        __half o = __float2half(0.f), o2 = o;
        if (kk < 16 && n < H_) {
            o  = __float2half(W1[(ks * 16 + kk) * H_ + n]);
            o2 = __float2half(W1[(128 + ks * 16 + kk) * H_ + n]);
        }
        g_W1h[i] = o;
        g_W1pw[i] = o2;
    }
    if (i < 9 * 144 * NSTRIDE) {
        int ks = i / (144 * NSTRIDE), r = i % (144 * NSTRIDE);
        int n = r / NSTRIDE, kk = r % NSTRIDE;
        int k = ks * 16 + kk;
        __half o = __float2half(0.f);
        if (kk < 16 && n < H_ && k < H_) o = __float2half(W2[k * H_ + n]);
        g_W2h[i] = o;
    }
    if (i < 9 * 64 * NSTRIDE) {
        int ks = i / (64 * NSTRIDE), r = i % (64 * NSTRIDE);
        int n = r / NSTRIDE, kk = r % NSTRIDE;
        int k = ks * 16 + kk;
        __half o = __float2half(0.f);
        if (kk < 16 && k < H_) o = __float2half(W3[k * O_ + n]);
        g_W3h[i] = o;
    }
    if (i < BB_ * T_ * O_) out[i] = 0.f;
    // phase-blocked 4-maxes
    if (i < 4 * 32 * BB_ * D_) {
        int p = i >> 17, j = (i >> 12) & 31, bb = (i >> 7) & 31, d = i & 127;
        int s0 = 4 * j + p;
        float m = -3.4e38f;
        #pragma unroll
        for (int q = 0; q < 4; ++q) {
            int s = s0 + q;
            if (s < T_) m = fmaxf(m, P[(bb * T_ + s) * D_ + d]);
        }
        g_B4[i] = m;
    }
}

// ---------------- pre level 2: scan phase blocks into g_pre4 ----------------
__global__ void pre_combine() {
    int idx = blockIdx.x * blockDim.x + threadIdx.x;   // T_*BB_*D_ = 524288
    int t = idx >> 12, bb = (idx >> 7) & 31, d = idx & 127;
    int p = t & 3, j0 = t >> 2;
    float run = -3.4e38f;
    int nci = 32 - j0;
    float* dst = g_pre4 + ((t * 32) * BB_ + bb) * D_ + d;
    const float* src = g_B4 + ((p * 32 + j0) * BB_ + bb) * D_ + d;
    for (int ci = 0; ci < nci; ++ci) {
        run = fmaxf(run, src[ci * (BB_ * D_)]);
        dst[ci * (BB_ * D_)] = run;
    }
}

// ---------------- barrier-free GEMM stage (MT m-tiles per warp) ----------------
template <int K16, int NT, int MT, int CHUNK, int XSTR>
__device__ __forceinline__ void gemm_stage(uint32_t wbase, float (*acc)[4],
                                           const uint32_t* aH, const uint32_t* bOff) {
    #pragma unroll
    for (int k = 0; k < K16; ++k) {
        uint32_t wb = wbase + k * CHUNK;
        uint32_t ah[MT][4];
        #pragma unroll
        for (int m = 0; m < MT; ++m) LDSM4(ah[m], aH[m] + k * XSTR);
        uint32_t b[2 * NT];
        if (NT == 9) {
            LDSM4(b, wb + bOff[0]); LDSM4(b + 4, wb + bOff[1]);
            LDSM4(b + 8, wb + bOff[2]); LDSM4(b + 12, wb + bOff[3]);
            LDSM2(b + 16, wb + bOff[4]);
        } else {
            LDSM4(b, wb + bOff[0]); LDSM4(b + 4, wb + bOff[1]);
        }
        #pragma unroll
        for (int j = 0; j < NT; ++j)
            #pragma unroll
            for (int m = 0; m < MT; ++m) mma_f16(acc[m * NT + j], ah[m], b + 2 * j);
    }
}

// ---------------- bulk weight loader ----------------
__device__ __forceinline__ void load_weights(uint32_t dst, const char* Wg, int bytes, int tid) {
    for (int off = tid * 16; off < bytes; off += 4096)
        CP16(dst + off, Wg + off);
    CP_COMMIT();
}

// ---------------- PW via tensor cores (1-pass fp16): g_PW = P·W1[128:256] + b1 ----------------
__global__ void __launch_bounds__(256, 2)
compute_pw_mma(const float* __restrict__ P, const float* __restrict__ b1) {
    const int s4 = blockIdx.x;
    const int nqh = blockIdx.y;
    extern __shared__ char smem[];
    uint32_t su = smem_u32(smem);
    const int tid = threadIdx.x;
    float* sB1 = (float*)(smem + PWK_B1);

    load_weights(su + PWK_W, (const char*)g_W1pw, WBYTES_A, tid);
    for (int i = tid; i < 144; i += 256) sB1[i] = (i < H_) ? b1[i] : 0.f;

    // X build: fp16 of P, vectorized (128 rows, 4096 B per kstep)
    {
        int p = tid & 63, g = tid >> 6;
        int d0 = 2 * p, ks = d0 >> 4, kk = d0 & 15;
        char* xh = smem;
        for (int b8 = 0; b8 < 8; ++b8) {
            int bb = g * 8 + b8;
            #pragma unroll
            for (int sl = 0; sl < 4; ++sl) {
                int s = s4 * 4 + sl;
                float2 pv = *(const float2*)&P[(bb * T_ + s) * D_ + d0];
                int row = sl * 32 + bb;
                int ph = (kk >> 3) ^ ((row >> 2) & 1);
                int off = ks * 4096 + row * 32 + ph * 16 + (kk & 7) * 2;
                __half2 h;
                h.x = __float2half(pv.x); h.y = __float2half(pv.y);
                *(__half2*)(xh + off) = h;
            }
        }
    }
    CP_WAIT0();
    __syncthreads();

    const int wid = tid >> 5, lane = tid & 31;
    const int m0 = wid * 16;                 // 8 m-quads, 1 m-tile each
    const int grp = lane >> 2, c0 = 2 * (lane & 3);

    uint32_t aH0, bAB[5];
    {
        int l15 = lane & 15, chnk = lane >> 4;
        int row = m0 + l15;
        int phys = chnk ^ ((row >> 2) & 1);
        aH0 = su + row * 32 + phys * 16;
        int l7 = lane & 7, kh = (lane >> 3) & 1, pr = (lane >> 4) & 1;
        #pragma unroll
        for (int i = 0; i < 4; ++i)
            bAB[i] = (uint32_t)((nqh * 72 + 16 * i + pr * 8 + l7) * 48 + kh * 16);
        bAB[4] = (uint32_t)((nqh * 72 + 64 + l7) * 48 + kh * 16);
    }

    float acc[9][4];
    #pragma unroll
    for (int i = 0; i < 9; ++i) { acc[i][0] = acc[i][1] = acc[i][2] = acc[i][3] = 0.f; }
    gemm_stage<8, 9, 1, WCH_AB, 4096>(su + PWK_W, acc, &aH0, bAB);

    #pragma unroll
    for (int rp = 0; rp < 2; ++rp) {
        int row = m0 + grp + rp * 8;
        int sl = row >> 5, bb = row & 31;
        int s = s4 * 4 + sl;
        #pragma unroll
        for (int j = 0; j < 9; ++j) {
            int n0 = nqh * 72 + j * 8 + c0;
            float2 v;
            v.x = acc[j][rp * 2 + 0] + sB1[n0];
            v.y = acc[j][rp * 2 + 1] + sB1[n0 + 1];
            *(float2*)&g_PW[(s * BB_ + bb) * 144 + n0] = v;
        }
    }
}

// ---------------- relu epilogue: write fp16 X tile for next stage ----------------
__device__ __forceinline__ void epi_relu(char* smem, float (*acc)[4], const float* bias,
                                         int m0, int nbase, int lane) {
    char* xh = smem + OFF_X;
    const int grp = lane >> 2;
    const int c0 = 2 * (lane & 3);
    #pragma unroll
    for (int mt = 0; mt < 2; ++mt)
    #pragma unroll
    for (int j = 0; j < 9; ++j) {
        int n0 = nbase + j * 8 + c0;
        float bv0 = bias ? bias[n0] : 0.f;
        float bv1 = bias ? bias[n0 + 1] : 0.f;
        int ks = n0 >> 4, kk = n0 & 15;
        #pragma unroll
        for (int rp = 0; rp < 2; ++rp) {
            int row = m0 + mt * 64 + grp + rp * 8;
            float v0 = fmaxf(acc[mt * 9 + j][rp * 2 + 0] + bv0, 0.f);
            float v1 = fmaxf(acc[mt * 9 + j][rp * 2 + 1] + bv1, 0.f);
            __half2 hp; hp.x = __float2half(v0); hp.y = __float2half(v1);
            *(__half2*)(xh + x_off(ks, row, kk)) = hp;
        }
    }
}

// ---------------- main ----------------
__global__ void __launch_bounds__(256, 2)
mlp_main_kernel(const float* __restrict__ P,
                const float* __restrict__ b2, const float* __restrict__ b3,
                float* __restrict__ out) {
    const int mc = g_map[blockIdx.x];
    const int t = mc >> 8;
    const int c = mc & 255;
    const int s0 = t + 4 * c;

    extern __shared__ char smem[];
    uint32_t su = smem_u32(smem);
    const int tid = threadIdx.x;
    float* sB2 = (float*)(smem + OFF_B2);
    float* sB3 = (float*)(smem + OFF_B3);

    load_weights(su + OFF_W, (const char*)g_W1h, WBYTES_A, tid);

    for (int i = tid; i < 144; i += 256) sB2[i] = (i < H_) ? b2[i] : 0.f;
    if (tid < 64) sB3[tid] = b3[tid];

    // feature build (vectorized): rows r = sl*32+bb; K cols [0,128) = running max, fp16
    {
        int p = tid & 63, g = tid >> 6;
        int d0 = 2 * p, ks = d0 >> 4, kk = d0 & 15;
        char* xh = smem + OFF_X;
        for (int b8 = 0; b8 < 8; ++b8) {
            int bb = g * 8 + b8;
            float2 run2;
            if (c > 0) run2 = *(const float2*)&g_pre4[((t * 32 + (c - 1)) * BB_ + bb) * D_ + d0];
            else { run2.x = -3.4e38f; run2.y = -3.4e38f; }
            #pragma unroll
            for (int sl = 0; sl < 4; ++sl) {
                int s = s0 + sl;
                if (s < T_) {
                    float2 pv = *(const float2*)&P[(bb * T_ + s) * D_ + d0];
                    run2.x = fmaxf(run2.x, pv.x);
                    run2.y = fmaxf(run2.y, pv.y);
                }
                int row = sl * 32 + bb;
                int ph = (kk >> 3) ^ ((row >> 2) & 1);
                int off = ks * 4096 + row * 32 + ph * 16 + (kk & 7) * 2;
                __half2 hp; hp.x = __float2half(run2.x); hp.y = __float2half(run2.y);
                *(__half2*)(xh + off) = hp;
            }
        }
    }

    const int wid = tid >> 5, lane = tid & 31;
    const int mq = wid >> 1, nq = wid & 1;      // 4 m-quads x 2 n-halves; m-tiles at m0, m0+64
    const int m0 = mq * 16;
    const int grp = lane >> 2, c0 = 2 * (lane & 3);

    float acc[18][4];

    // Stage A: acc preloaded from PW (P-part + b1) — BEFORE the wait, overlaps cp.async
    #pragma unroll
    for (int mt = 0; mt < 2; ++mt) {
        int r_lo = m0 + mt * 64 + grp, r_hi = r_lo + 8;
        int s_lo = min(s0 + (r_lo >> 5), T_ - 1), s_hi = min(s0 + (r_hi >> 5), T_ - 1);
        const float* pwlo = g_PW + (s_lo * BB_ + (r_lo & 31)) * 144;
        const float* pwhi = g_PW + (s_hi * BB_ + (r_hi & 31)) * 144;
        #pragma unroll
        for (int j = 0; j < 9; ++j) {
            int n0 = nq * 72 + j * 8 + c0;
            float2 vlo = *(const float2*)(pwlo + n0);
            float2 vhi = *(const float2*)(pwhi + n0);
            acc[mt * 9 + j][0] = vlo.x; acc[mt * 9 + j][1] = vlo.y;
            acc[mt * 9 + j][2] = vhi.x; acc[mt * 9 + j][3] = vhi.y;
        }
    }

    // per-lane ldmatrix addresses
    uint32_t aH[2], bAB[5], bC[2];
    {
        int l15 = lane & 15, chnk = lane >> 4;
        #pragma unroll
        for (int mt = 0; mt < 2; ++mt) {
            int row = m0 + mt * 64 + l15;
            int phys = chnk ^ ((row >> 2) & 1);
            aH[mt] = su + OFF_X + row * 32 + phys * 16;
        }
        int l7 = lane & 7, kh = (lane >> 3) & 1, pr = (lane >> 4) & 1;
        #pragma unroll
        for (int i = 0; i < 4; ++i)
            bAB[i] = (uint32_t)((nq * 72 + 16 * i + pr * 8 + l7) * 48 + kh * 16);
        bAB[4] = (uint32_t)((nq * 72 + 64 + l7) * 48 + kh * 16);
        #pragma unroll
        for (int i = 0; i < 2; ++i)
            bC[i] = (uint32_t)((nq * 32 + 16 * i + pr * 8 + l7) * 48 + kh * 16);
    }

    CP_WAIT0();
    __syncthreads();

    // Stage A: K=128 (8 ksteps), N=144
    gemm_stage<8, 9, 2, WCH_AB, 4096>(su + OFF_W, acc, aH, bAB);
    __syncthreads();
    load_weights(su + OFF_W, (const char*)g_W2h, WBYTES_B, tid);   // hide behind epi A
    epi_relu(smem, acc, (const float*)0, m0, nq * 72, lane);
    CP_WAIT0();
    __syncthreads();

    // Stage B: K=144 (9 ksteps), N=144
    #pragma unroll
    for (int i = 0; i < 18; ++i) { acc[i][0] = acc[i][1] = acc[i][2] = acc[i][3] = 0.f; }
    gemm_stage<9, 9, 2, WCH_AB, 4096>(su + OFF_W, acc, aH, bAB);
    __syncthreads();
    load_weights(su + OFF_W, (const char*)g_W3h, WBYTES_C, tid);   // hide behind epi B
    epi_relu(smem, acc, sB2, m0, nq * 72, lane);
    CP_WAIT0();
    __syncthreads();

    // Stage C: K=144 (9 ksteps), N=64
    #pragma unroll
    for (int i = 0; i < 8; ++i) { acc[i][0] = acc[i][1] = acc[i][2] = acc[i][3] = 0.f; }
    gemm_stage<9, 4, 2, WCH_C, 4096>(su + OFF_W, acc, aH, bC);

    // final epilogue: sigmoid + DIRECT global max reduce (no smem staging, no barriers)
    float* outT = out + t * O_;
    #pragma unroll
    for (int mt = 0; mt < 2; ++mt)
    #pragma unroll
    for (int rp = 0; rp < 2; ++rp) {
        int row = m0 + mt * 64 + grp + rp * 8;
        int sl = row >> 5, bb = row & 31;
        if (s0 + sl < T_) {
            int* op = (int*)(outT + bb * (T_ * O_));
            #pragma unroll
            for (int j = 0; j < 4; ++j) {
                int n0 = nq * 32 + j * 8 + c0;
                float y0 = 1.f / (1.f + __expf(-5.f * (acc[mt * 4 + j][rp * 2 + 0] + sB3[n0])));
                float y1 = 1.f / (1.f + __expf(-5.f * (acc[mt * 4 + j][rp * 2 + 1] + sB3[n0 + 1])));
                atomicMax(op + n0, __float_as_int(y0));
                atomicMax(op + n0 + 1, __float_as_int(y1));
            }
        }
    }
}

// ---------------- launch ----------------
extern "C" void kernel_launch(void* const* d_in, const int* in_sizes, int n_in,
                              void* d_out, int out_size) {
    const float* P  = (const float*)d_in[0];
    const float* W1 = (const float*)d_in[1];
    const float* b1 = (const float*)d_in[2];
    const float* W2 = (const float*)d_in[3];
    const float* b2 = (const float*)d_in[4];
    const float* W3 = (const float*)d_in[5];
    const float* b3 = (const float*)d_in[6];
    float* out = (float*)d_out;

    cudaFuncSetAttribute(mlp_main_kernel, cudaFuncAttributeMaxDynamicSharedMemorySize, SMEM_TOTAL);
    cudaFuncSetAttribute(compute_pw_mma, cudaFuncAttributeMaxDynamicSharedMemorySize, PWK_SMEM);

    prep_all<<<(4 * 32 * BB_ * D_) / 256, 256>>>(W1, W2, W3, P, out);
    pre_combine<<<(T_ * BB_ * D_) / 256, 256>>>();
    compute_pw_mma<<<dim3(32, 2), 256, PWK_SMEM>>>(P, b1);
    mlp_main_kernel<<<NBLK, 256, SMEM_TOTAL>>>(P, b2, b3, out);
}

// round 16
// speedup vs baseline: 1.0852x; 1.0852x over previous
#include <cuda_runtime.h>
#include <cuda_fp16.h>
#include <math.h>
#include <stdint.h>

#define BB_ 32
#define T_ 128
#define D_ 128
#define H_ 132
#define O_ 64

#define NSTRIDE 24                    // fp16 per n-row (48B): [16 k-vals][8B pad] -> ldmatrix conflict-free
#define WCH_AB (144 * 48)             // 6912 B per k-step chunk (N=144)
#define WCH_C  (64 * 48)              // 3072 B per k-step chunk (N=64)
#define WBYTES_A (8 * WCH_AB)         // 55296
#define WBYTES_B (9 * WCH_AB)         // 62208
#define WBYTES_C (9 * WCH_C)          // 27648

// ---------------- main-kernel SMEM layout ----------------
#define OFF_X   0                     // 9 ksteps x 128 rows x 32B = 36864
#define OFF_W   36864                 // whole-stage weights, max 62208 -> 99072
#define OFF_B2  99072                 // 144 floats -> 99648
#define OFF_B3  99648                 // 64 floats  -> 99904
#define OFF_RED OFF_X                 // sRed (8192B) ALIASES X tile; used only after stage C
#define SMEM_TOTAL 99904              // x2 blocks = 199808 < 228KB/SM

// ---------------- PW-kernel SMEM layout (1-pass: X hi only) ----------------
#define PWK_W   32768                 // X (32768) then W (55296) -> 88064
#define PWK_B1  88064                 // 144 floats -> 88640
#define PWK_SMEM 88640                // x2 blocks = 177280

#define NBLK 2112                     // sum_t ceil((128-t)/4)

// ---------------- device scratch ----------------
__device__ float g_B4[4 * 32 * BB_ * D_];      // [p][j][bb][d]: max P over s in [4j+p, 4j+4+p)
__device__ float g_pre4[T_ * 32 * BB_ * D_];   // [t][ci][bb][d]: max over [t, t+4(ci+1))
__device__ float g_PW[T_ * BB_ * 144];         // [s][bb][n]: P(s,bb)·W1[128:256] + b1
__device__ __half g_W1h[8 * 144 * NSTRIDE];    // [kstep][n][24], W1 rows 0..127 (M part), fp16
__device__ __half g_W1pw[8 * 144 * NSTRIDE];   // [kstep][n][24], W1 rows 128..255 (P part), fp16
__device__ __half g_W2h[9 * 144 * NSTRIDE];
__device__ __half g_W3h[9 * 64 * NSTRIDE];
__device__ int g_map[NBLK];                    // packed (t<<8)|c

// ---------------- asm helpers ----------------
__device__ __forceinline__ void mma_f16(float d[4], const uint32_t a[4], const uint32_t b[2]) {
    asm volatile("mma.sync.aligned.m16n8k16.row.col.f32.f16.f16.f32 "
                 "{%0,%1,%2,%3}, {%4,%5,%6,%7}, {%8,%9}, {%0,%1,%2,%3};"
                 : "+f"(d[0]), "+f"(d[1]), "+f"(d[2]), "+f"(d[3])
                 : "r"(a[0]), "r"(a[1]), "r"(a[2]), "r"(a[3]), "r"(b[0]), "r"(b[1]));
}
__device__ __forceinline__ uint32_t smem_u32(const void* p) {
    uint32_t a;
    asm("{ .reg .u64 t; cvta.to.shared.u64 t, %1; cvt.u32.u64 %0, t; }" : "=r"(a) : "l"(p));
    return a;
}
#define CP16(dst, src) asm volatile("cp.async.ca.shared.global [%0], [%1], 16;" :: "r"(dst), "l"(src) : "memory")
#define CP_COMMIT()    asm volatile("cp.async.commit_group;" ::: "memory")
#define CP_WAIT0()     asm volatile("cp.async.wait_group 0;" ::: "memory")
#define LDSM4(r, a) asm volatile("ldmatrix.sync.aligned.m8n8.x4.shared.b16 {%0,%1,%2,%3}, [%4];" \
    : "=r"((r)[0]), "=r"((r)[1]), "=r"((r)[2]), "=r"((r)[3]) : "r"(a))
#define LDSM2(r, a) asm volatile("ldmatrix.sync.aligned.m8n8.x2.shared.b16 {%0,%1}, [%2];" \
    : "=r"((r)[0]), "=r"((r)[1]) : "r"(a))

// X element address with 16B-half swizzle (ldmatrix conflict-free); 128 rows/kstep
__device__ __forceinline__ int x_off(int ks, int row, int kk) {
    int phys = (kk >> 3) ^ ((row >> 2) & 1);
    return ks * 4096 + row * 32 + phys * 16 + (kk & 7) * 2;
}

// ---------------- prep: weights + tile map + phase-blocked 4-maxes + out init ----------------
__global__ void prep_all(const float* __restrict__ W1, const float* __restrict__ W2,
                         const float* __restrict__ W3, const float* __restrict__ P,
                         float* __restrict__ out) {
    int i = blockIdx.x * blockDim.x + threadIdx.x;
    if (blockIdx.x == 0 && threadIdx.x < 128) {
        int t = threadIdx.x;
        int start = 0;
        for (int u = 0; u < t; ++u) start += (131 - u) >> 2;
        int nch = (131 - t) >> 2;
        for (int c2 = 0; c2 < nch; ++c2) g_map[start + c2] = (t << 8) | c2;
    }
    if (i < 8 * 144 * NSTRIDE) {
        int ks = i / (144 * NSTRIDE), r = i % (144 * NSTRIDE);
        int n = r / NSTRIDE, kk = r % NSTRIDE;
        __half o = __float2half(0.f), o2 = o;
        if (kk < 16 && n < H_) {
            o  = __float2half(W1[(ks * 16 + kk) * H_ + n]);
            o2 = __float2half(W1[(128 + ks * 16 + kk) * H_ + n]);
        }
        g_W1h[i] = o;
        g_W1pw[i] = o2;
    }
    if (i < 9 * 144 * NSTRIDE) {
        int ks = i / (144 * NSTRIDE), r = i % (144 * NSTRIDE);
        int n = r / NSTRIDE, kk = r % NSTRIDE;
        int k = ks * 16 + kk;
        __half o = __float2half(0.f);
        if (kk < 16 && n < H_ && k < H_) o = __float2half(W2[k * H_ + n]);
        g_W2h[i] = o;
    }
    if (i < 9 * 64 * NSTRIDE) {
        int ks = i / (64 * NSTRIDE), r = i % (64 * NSTRIDE);
        int n = r / NSTRIDE, kk = r % NSTRIDE;
        int k = ks * 16 + kk;
        __half o = __float2half(0.f);
        if (kk < 16 && k < H_) o = __float2half(W3[k * O_ + n]);
        g_W3h[i] = o;
    }
    if (i < BB_ * T_ * O_) out[i] = 0.f;
    // phase-blocked 4-maxes
    if (i < 4 * 32 * BB_ * D_) {
        int p = i >> 17, j = (i >> 12) & 31, bb = (i >> 7) & 31, d = i & 127;
        int s0 = 4 * j + p;
        float m = -3.4e38f;
        #pragma unroll
        for (int q = 0; q < 4; ++q) {
            int s = s0 + q;
            if (s < T_) m = fmaxf(m, P[(bb * T_ + s) * D_ + d]);
        }
        g_B4[i] = m;
    }
}

// ---------------- pre level 2: scan phase blocks into g_pre4 ----------------
__global__ void pre_combine() {
    int idx = blockIdx.x * blockDim.x + threadIdx.x;   // T_*BB_*D_ = 524288
    int t = idx >> 12, bb = (idx >> 7) & 31, d = idx & 127;
    int p = t & 3, j0 = t >> 2;
    float run = -3.4e38f;
    int nci = 32 - j0;
    float* dst = g_pre4 + ((t * 32) * BB_ + bb) * D_ + d;
    const float* src = g_B4 + ((p * 32 + j0) * BB_ + bb) * D_ + d;
    for (int ci = 0; ci < nci; ++ci) {
        run = fmaxf(run, src[ci * (BB_ * D_)]);
        dst[ci * (BB_ * D_)] = run;
    }
}

// ---------------- barrier-free GEMM stage (MT m-tiles per warp) ----------------
template <int K16, int NT, int MT, int CHUNK, int XSTR>
__device__ __forceinline__ void gemm_stage(uint32_t wbase, float (*acc)[4],
                                           const uint32_t* aH, const uint32_t* bOff) {
    #pragma unroll
    for (int k = 0; k < K16; ++k) {
        uint32_t wb = wbase + k * CHUNK;
        uint32_t ah[MT][4];
        #pragma unroll
        for (int m = 0; m < MT; ++m) LDSM4(ah[m], aH[m] + k * XSTR);
        uint32_t b[2 * NT];
        if (NT == 9) {
            LDSM4(b, wb + bOff[0]); LDSM4(b + 4, wb + bOff[1]);
            LDSM4(b + 8, wb + bOff[2]); LDSM4(b + 12, wb + bOff[3]);
            LDSM2(b + 16, wb + bOff[4]);
        } else {
            LDSM4(b, wb + bOff[0]); LDSM4(b + 4, wb + bOff[1]);
        }
        #pragma unroll
        for (int j = 0; j < NT; ++j)
            #pragma unroll
            for (int m = 0; m < MT; ++m) mma_f16(acc[m * NT + j], ah[m], b + 2 * j);
    }
}

// ---------------- bulk weight loader ----------------
__device__ __forceinline__ void load_weights(uint32_t dst, const char* Wg, int bytes, int tid) {
    for (int off = tid * 16; off < bytes; off += 4096)
        CP16(dst + off, Wg + off);
    CP_COMMIT();
}

// ---------------- PW via tensor cores (1-pass fp16): g_PW = P·W1[128:256] + b1 ----------------
__global__ void __launch_bounds__(256, 2)
compute_pw_mma(const float* __restrict__ P, const float* __restrict__ b1) {
    const int s4 = blockIdx.x;
    const int nqh = blockIdx.y;
    extern __shared__ char smem[];
    uint32_t su = smem_u32(smem);
    const int tid = threadIdx.x;
    float* sB1 = (float*)(smem + PWK_B1);

    load_weights(su + PWK_W, (const char*)g_W1pw, WBYTES_A, tid);
    for (int i = tid; i < 144; i += 256) sB1[i] = (i < H_) ? b1[i] : 0.f;

    // X build: fp16 of P, vectorized (128 rows, 4096 B per kstep)
    {
        int p = tid & 63, g = tid >> 6;
        int d0 = 2 * p, ks = d0 >> 4, kk = d0 & 15;
        char* xh = smem;
        for (int b8 = 0; b8 < 8; ++b8) {
            int bb = g * 8 + b8;
            #pragma unroll
            for (int sl = 0; sl < 4; ++sl) {
                int s = s4 * 4 + sl;
                float2 pv = *(const float2*)&P[(bb * T_ + s) * D_ + d0];
                int row = sl * 32 + bb;
                int ph = (kk >> 3) ^ ((row >> 2) & 1);
                int off = ks * 4096 + row * 32 + ph * 16 + (kk & 7) * 2;
                __half2 h;
                h.x = __float2half(pv.x); h.y = __float2half(pv.y);
                *(__half2*)(xh + off) = h;
            }
        }
    }
    CP_WAIT0();
    __syncthreads();

    const int wid = tid >> 5, lane = tid & 31;
    const int m0 = wid * 16;                 // 8 m-quads, 1 m-tile each
    const int grp = lane >> 2, c0 = 2 * (lane & 3);

    uint32_t aH0, bAB[5];
    {
        int l15 = lane & 15, chnk = lane >> 4;
        int row = m0 + l15;
        int phys = chnk ^ ((row >> 2) & 1);
        aH0 = su + row * 32 + phys * 16;
        int l7 = lane & 7, kh = (lane >> 3) & 1, pr = (lane >> 4) & 1;
        #pragma unroll
        for (int i = 0; i < 4; ++i)
            bAB[i] = (uint32_t)((nqh * 72 + 16 * i + pr * 8 + l7) * 48 + kh * 16);
        bAB[4] = (uint32_t)((nqh * 72 + 64 + l7) * 48 + kh * 16);
    }

    float acc[9][4];
    #pragma unroll
    for (int i = 0; i < 9; ++i) { acc[i][0] = acc[i][1] = acc[i][2] = acc[i][3] = 0.f; }
    gemm_stage<8, 9, 1, WCH_AB, 4096>(su + PWK_W, acc, &aH0, bAB);

    #pragma unroll
    for (int rp = 0; rp < 2; ++rp) {
        int row = m0 + grp + rp * 8;
        int sl = row >> 5, bb = row & 31;
        int s = s4 * 4 + sl;
        #pragma unroll
        for (int j = 0; j < 9; ++j) {
            int n0 = nqh * 72 + j * 8 + c0;
            float2 v;
            v.x = acc[j][rp * 2 + 0] + sB1[n0];
            v.y = acc[j][rp * 2 + 1] + sB1[n0 + 1];
            *(float2*)&g_PW[(s * BB_ + bb) * 144 + n0] = v;
        }
    }
}

// ---------------- relu epilogue: write fp16 X tile for next stage ----------------
__device__ __forceinline__ void epi_relu(char* smem, float (*acc)[4], const float* bias,
                                         int m0, int nbase, int lane) {
    char* xh = smem + OFF_X;
    const int grp = lane >> 2;
    const int c0 = 2 * (lane & 3);
    #pragma unroll
    for (int mt = 0; mt < 2; ++mt)
    #pragma unroll
    for (int j = 0; j < 9; ++j) {
        int n0 = nbase + j * 8 + c0;
        float bv0 = bias ? bias[n0] : 0.f;
        float bv1 = bias ? bias[n0 + 1] : 0.f;
        int ks = n0 >> 4, kk = n0 & 15;
        #pragma unroll
        for (int rp = 0; rp < 2; ++rp) {
            int row = m0 + mt * 64 + grp + rp * 8;
            float v0 = fmaxf(acc[mt * 9 + j][rp * 2 + 0] + bv0, 0.f);
            float v1 = fmaxf(acc[mt * 9 + j][rp * 2 + 1] + bv1, 0.f);
            __half2 hp; hp.x = __float2half(v0); hp.y = __float2half(v1);
            *(__half2*)(xh + x_off(ks, row, kk)) = hp;
        }
    }
}

// ---------------- main ----------------
__global__ void __launch_bounds__(256, 2)
mlp_main_kernel(const float* __restrict__ P,
                const float* __restrict__ b2, const float* __restrict__ b3,
                float* __restrict__ out) {
    const int mc = g_map[blockIdx.x];
    const int t = mc >> 8;
    const int c = mc & 255;
    const int s0 = t + 4 * c;

    extern __shared__ char smem[];
    uint32_t su = smem_u32(smem);
    const int tid = threadIdx.x;
    float* sB2 = (float*)(smem + OFF_B2);
    float* sB3 = (float*)(smem + OFF_B3);
    int* sRed = (int*)(smem + OFF_RED);    // ALIASES X tile; valid only after stage C

    load_weights(su + OFF_W, (const char*)g_W1h, WBYTES_A, tid);

    for (int i = tid; i < 144; i += 256) sB2[i] = (i < H_) ? b2[i] : 0.f;
    if (tid < 64) sB3[tid] = b3[tid];

    // feature build (vectorized): rows r = sl*32+bb; K cols [0,128) = running max, fp16
    {
        int p = tid & 63, g = tid >> 6;
        int d0 = 2 * p, ks = d0 >> 4, kk = d0 & 15;
        char* xh = smem + OFF_X;
        for (int b8 = 0; b8 < 8; ++b8) {
            int bb = g * 8 + b8;
            float2 run2;
            if (c > 0) run2 = *(const float2*)&g_pre4[((t * 32 + (c - 1)) * BB_ + bb) * D_ + d0];
            else { run2.x = -3.4e38f; run2.y = -3.4e38f; }
            #pragma unroll
            for (int sl = 0; sl < 4; ++sl) {
                int s = s0 + sl;
                if (s < T_) {
                    float2 pv = *(const float2*)&P[(bb * T_ + s) * D_ + d0];
                    run2.x = fmaxf(run2.x, pv.x);
                    run2.y = fmaxf(run2.y, pv.y);
                }
                int row = sl * 32 + bb;
                int ph = (kk >> 3) ^ ((row >> 2) & 1);
                int off = ks * 4096 + row * 32 + ph * 16 + (kk & 7) * 2;
                __half2 hp; hp.x = __float2half(run2.x); hp.y = __float2half(run2.y);
                *(__half2*)(xh + off) = hp;
            }
        }
    }

    const int wid = tid >> 5, lane = tid & 31;
    const int mq = wid >> 1, nq = wid & 1;      // 4 m-quads x 2 n-halves; m-tiles at m0, m0+64
    const int m0 = mq * 16;
    const int grp = lane >> 2, c0 = 2 * (lane & 3);

    float acc[18][4];

    // Stage A: acc preloaded from PW (P-part + b1) — BEFORE the wait, overlaps cp.async
    #pragma unroll
    for (int mt = 0; mt < 2; ++mt) {
        int r_lo = m0 + mt * 64 + grp, r_hi = r_lo + 8;
        int s_lo = min(s0 + (r_lo >> 5), T_ - 1), s_hi = min(s0 + (r_hi >> 5), T_ - 1);
        const float* pwlo = g_PW + (s_lo * BB_ + (r_lo & 31)) * 144;
        const float* pwhi = g_PW + (s_hi * BB_ + (r_hi & 31)) * 144;
        #pragma unroll
        for (int j = 0; j < 9; ++j) {
            int n0 = nq * 72 + j * 8 + c0;
            float2 vlo = *(const float2*)(pwlo + n0);
            float2 vhi = *(const float2*)(pwhi + n0);
            acc[mt * 9 + j][0] = vlo.x; acc[mt * 9 + j][1] = vlo.y;
            acc[mt * 9 + j][2] = vhi.x; acc[mt * 9 + j][3] = vhi.y;
        }
    }

    // per-lane ldmatrix addresses
    uint32_t aH[2], bAB[5], bC[2];
    {
        int l15 = lane & 15, chnk = lane >> 4;
        #pragma unroll
        for (int mt = 0; mt < 2; ++mt) {
            int row = m0 + mt * 64 + l15;
            int phys = chnk ^ ((row >> 2) & 1);
            aH[mt] = su + OFF_X + row * 32 + phys * 16;
        }
        int l7 = lane & 7, kh = (lane >> 3) & 1, pr = (lane >> 4) & 1;
        #pragma unroll
        for (int i = 0; i < 4; ++i)
            bAB[i] = (uint32_t)((nq * 72 + 16 * i + pr * 8 + l7) * 48 + kh * 16);
        bAB[4] = (uint32_t)((nq * 72 + 64 + l7) * 48 + kh * 16);
        #pragma unroll
        for (int i = 0; i < 2; ++i)
            bC[i] = (uint32_t)((nq * 32 + 16 * i + pr * 8 + l7) * 48 + kh * 16);
    }

    CP_WAIT0();
    __syncthreads();

    // Stage A: K=128 (8 ksteps), N=144
    gemm_stage<8, 9, 2, WCH_AB, 4096>(su + OFF_W, acc, aH, bAB);
    __syncthreads();
    load_weights(su + OFF_W, (const char*)g_W2h, WBYTES_B, tid);   // hide behind epi A
    epi_relu(smem, acc, (const float*)0, m0, nq * 72, lane);
    CP_WAIT0();
    __syncthreads();

    // Stage B: K=144 (9 ksteps), N=144
    #pragma unroll
    for (int i = 0; i < 18; ++i) { acc[i][0] = acc[i][1] = acc[i][2] = acc[i][3] = 0.f; }
    gemm_stage<9, 9, 2, WCH_AB, 4096>(su + OFF_W, acc, aH, bAB);
    __syncthreads();
    load_weights(su + OFF_W, (const char*)g_W3h, WBYTES_C, tid);   // hide behind epi B
    epi_relu(smem, acc, sB2, m0, nq * 72, lane);
    CP_WAIT0();
    __syncthreads();

    // Stage C: K=144 (9 ksteps), N=64
    #pragma unroll
    for (int i = 0; i < 8; ++i) { acc[i][0] = acc[i][1] = acc[i][2] = acc[i][3] = 0.f; }
    gemm_stage<9, 4, 2, WCH_C, 4096>(su + OFF_W, acc, aH, bC);

    // X tile is dead now; init the aliased reduction buffer, then reduce
    __syncthreads();
    for (int i = tid; i < BB_ * O_; i += 256) sRed[i] = 0;
    __syncthreads();

    // final epilogue: sigmoid + smem max reduce (1 global atomic per (bb,o))
    {
        #pragma unroll
        for (int mt = 0; mt < 2; ++mt)
        #pragma unroll
        for (int rp = 0; rp < 2; ++rp) {
            int row = m0 + mt * 64 + grp + rp * 8;
            int sl = row >> 5, bb = row & 31;
            if (s0 + sl < T_) {
                #pragma unroll
                for (int j = 0; j < 4; ++j) {
                    int n0 = nq * 32 + j * 8 + c0;
                    float y0 = 1.f / (1.f + __expf(-5.f * (acc[mt * 4 + j][rp * 2 + 0] + sB3[n0])));
                    float y1 = 1.f / (1.f + __expf(-5.f * (acc[mt * 4 + j][rp * 2 + 1] + sB3[n0 + 1])));
                    atomicMax(&sRed[bb * O_ + n0], __float_as_int(y0));
                    atomicMax(&sRed[bb * O_ + n0 + 1], __float_as_int(y1));
                }
            }
        }
    }
    __syncthreads();
    for (int i = tid; i < BB_ * O_; i += 256) {
        int bb = i >> 6, o = i & 63;
        atomicMax((int*)(out + (bb * T_ + t) * O_ + o), sRed[i]);
    }
}

// ---------------- launch ----------------
extern "C" void kernel_launch(void* const* d_in, const int* in_sizes, int n_in,
                              void* d_out, int out_size) {
    const float* P  = (const float*)d_in[0];
    const float* W1 = (const float*)d_in[1];
    const float* b1 = (const float*)d_in[2];
    const float* W2 = (const float*)d_in[3];
    const float* b2 = (const float*)d_in[4];
    const float* W3 = (const float*)d_in[5];
    const float* b3 = (const float*)d_in[6];
    float* out = (float*)d_out;

    cudaFuncSetAttribute(mlp_main_kernel, cudaFuncAttributeMaxDynamicSharedMemorySize, SMEM_TOTAL);
    cudaFuncSetAttribute(compute_pw_mma, cudaFuncAttributeMaxDynamicSharedMemorySize, PWK_SMEM);

    prep_all<<<(4 * 32 * BB_ * D_) / 256, 256>>>(W1, W2, W3, P, out);
    pre_combine<<<(T_ * BB_ * D_) / 256, 256>>>();
    compute_pw_mma<<<dim3(32, 2), 256, PWK_SMEM>>>(P, b1);
    mlp_main_kernel<<<NBLK, 256, SMEM_TOTAL>>>(P, b2, b3, out);
}

// round 17
// speedup vs baseline: 1.1709x; 1.0791x over previous
#include <cuda_runtime.h>
#include <cuda_fp16.h>
#include <math.h>
#include <stdint.h>

#define BB_ 32
#define T_ 128
#define D_ 128
#define H_ 132
#define O_ 64

#define NSTRIDE 24                    // fp16 per n-row (48B): [16 k-vals][8B pad] -> ldmatrix conflict-free
#define WCH_AB (144 * 48)             // 6912 B per k-step chunk (N=144)
#define WCH_C  (64 * 48)              // 3072 B per k-step chunk (N=64)
#define WBYTES_A (8 * WCH_AB)         // 55296
#define WBYTES_B (9 * WCH_AB)         // 62208
#define WBYTES_C (9 * WCH_C)          // 27648

#define XSTR 4128                     // X k-step stride: 4096 + 32B skew -> bank-rotated per kstep

// ---------------- main-kernel SMEM layout ----------------
#define OFF_X   0                     // 9 ksteps x 4128 = 37152
#define OFF_W   37152                 // whole-stage weights, max 62208 -> 99360
#define OFF_RED (OFF_W + 28672)       // sRed (8192B): beyond stage-C weights (27648), inside W buf
#define OFF_B2  99360                 // 144 floats -> 99936
#define OFF_B3  99936                 // 64 floats  -> 100192
#define SMEM_TOTAL 100192             // x2 blocks = 200384 < 228KB/SM

// ---------------- PW-kernel SMEM layout (1-pass: X hi only) ----------------
#define PWK_W   33024                 // X (8 x 4128 = 33024) then W (55296) -> 88320
#define PWK_B1  88320                 // 144 floats -> 88896
#define PWK_SMEM 88896

#define NBLK 2112                     // sum_t ceil((128-t)/4)

// ---------------- device scratch ----------------
__device__ float g_B4[4 * 32 * BB_ * D_];      // [p][j][bb][d]: max P over s in [4j+p, 4j+4+p)
__device__ float g_pre4[T_ * 32 * BB_ * D_];   // [t][ci][bb][d]: max over [t, t+4(ci+1))
__device__ float g_PW[T_ * BB_ * 144];         // [s][bb][n]: P(s,bb)·W1[128:256] + b1
__device__ __half g_W1h[8 * 144 * NSTRIDE];    // [kstep][n][24], W1 rows 0..127 (M part), fp16
__device__ __half g_W1pw[8 * 144 * NSTRIDE];   // [kstep][n][24], W1 rows 128..255 (P part), fp16
__device__ __half g_W2h[9 * 144 * NSTRIDE];
__device__ __half g_W3h[9 * 64 * NSTRIDE];
__device__ int g_map[NBLK];                    // packed (t<<8)|c

// ---------------- asm helpers ----------------
__device__ __forceinline__ void mma_f16(float d[4], const uint32_t a[4], const uint32_t b[2]) {
    asm volatile("mma.sync.aligned.m16n8k16.row.col.f32.f16.f16.f32 "
                 "{%0,%1,%2,%3}, {%4,%5,%6,%7}, {%8,%9}, {%0,%1,%2,%3};"
                 : "+f"(d[0]), "+f"(d[1]), "+f"(d[2]), "+f"(d[3])
                 : "r"(a[0]), "r"(a[1]), "r"(a[2]), "r"(a[3]), "r"(b[0]), "r"(b[1]));
}
__device__ __forceinline__ uint32_t smem_u32(const void* p) {
    uint32_t a;
    asm("{ .reg .u64 t; cvta.to.shared.u64 t, %1; cvt.u32.u64 %0, t; }" : "=r"(a) : "l"(p));
    return a;
}
#define CP16(dst, src) asm volatile("cp.async.ca.shared.global [%0], [%1], 16;" :: "r"(dst), "l"(src) : "memory")
#define CP_COMMIT()    asm volatile("cp.async.commit_group;" ::: "memory")
#define CP_WAIT0()     asm volatile("cp.async.wait_group 0;" ::: "memory")
#define LDSM4(r, a) asm volatile("ldmatrix.sync.aligned.m8n8.x4.shared.b16 {%0,%1,%2,%3}, [%4];" \
    : "=r"((r)[0]), "=r"((r)[1]), "=r"((r)[2]), "=r"((r)[3]) : "r"(a))
#define LDSM2(r, a) asm volatile("ldmatrix.sync.aligned.m8n8.x2.shared.b16 {%0,%1}, [%2];" \
    : "=r"((r)[0]), "=r"((r)[1]) : "r"(a))

// X element address (stride XSTR per kstep) with 16B-half swizzle
__device__ __forceinline__ int x_off(int ks, int row, int kk) {
    int phys = (kk >> 3) ^ ((row >> 2) & 1);
    return ks * XSTR + row * 32 + phys * 16 + (kk & 7) * 2;
}

// ---------------- prep: weights + tile map + phase-blocked 4-maxes + out init ----------------
__global__ void prep_all(const float* __restrict__ W1, const float* __restrict__ W2,
                         const float* __restrict__ W3, const float* __restrict__ P,
                         float* __restrict__ out) {
    int i = blockIdx.x * blockDim.x + threadIdx.x;
    if (blockIdx.x == 0 && threadIdx.x < 128) {
        int t = threadIdx.x;
        int start = 0;
        for (int u = 0; u < t; ++u) start += (131 - u) >> 2;
        int nch = (131 - t) >> 2;
        for (int c2 = 0; c2 < nch; ++c2) g_map[start + c2] = (t << 8) | c2;
    }
    if (i < 8 * 144 * NSTRIDE) {
        int ks = i / (144 * NSTRIDE), r = i % (144 * NSTRIDE);
        int n = r / NSTRIDE, kk = r % NSTRIDE;
        __half o = __float2half(0.f), o2 = o;
        if (kk < 16 && n < H_) {
            o  = __float2half(W1[(ks * 16 + kk) * H_ + n]);
            o2 = __float2half(W1[(128 + ks * 16 + kk) * H_ + n]);
        }
        g_W1h[i] = o;
        g_W1pw[i] = o2;
    }
    if (i < 9 * 144 * NSTRIDE) {
        int ks = i / (144 * NSTRIDE), r = i % (144 * NSTRIDE);
        int n = r / NSTRIDE, kk = r % NSTRIDE;
        int k = ks * 16 + kk;
        __half o = __float2half(0.f);
        if (kk < 16 && n < H_ && k < H_) o = __float2half(W2[k * H_ + n]);
        g_W2h[i] = o;
    }
    if (i < 9 * 64 * NSTRIDE) {
        int ks = i / (64 * NSTRIDE), r = i % (64 * NSTRIDE);
        int n = r / NSTRIDE, kk = r % NSTRIDE;
        int k = ks * 16 + kk;
        __half o = __float2half(0.f);
        if (kk < 16 && k < H_) o = __float2half(W3[k * O_ + n]);
        g_W3h[i] = o;
    }
    if (i < BB_ * T_ * O_) out[i] = 0.f;
    // phase-blocked 4-maxes
    if (i < 4 * 32 * BB_ * D_) {
        int p = i >> 17, j = (i >> 12) & 31, bb = (i >> 7) & 31, d = i & 127;
        int s0 = 4 * j + p;
        float m = -3.4e38f;
        #pragma unroll
        for (int q = 0; q < 4; ++q) {
            int s = s0 + q;
            if (s < T_) m = fmaxf(m, P[(bb * T_ + s) * D_ + d]);
        }
        g_B4[i] = m;
    }
}

// ---------------- pre level 2: scan phase blocks into g_pre4 ----------------
__global__ void pre_combine() {
    int idx = blockIdx.x * blockDim.x + threadIdx.x;   // T_*BB_*D_ = 524288
    int t = idx >> 12, bb = (idx >> 7) & 31, d = idx & 127;
    int p = t & 3, j0 = t >> 2;
    float run = -3.4e38f;
    int nci = 32 - j0;
    float* dst = g_pre4 + ((t * 32) * BB_ + bb) * D_ + d;
    const float* src = g_B4 + ((p * 32 + j0) * BB_ + bb) * D_ + d;
    for (int ci = 0; ci < nci; ++ci) {
        run = fmaxf(run, src[ci * (BB_ * D_)]);
        dst[ci * (BB_ * D_)] = run;
    }
}

// ---------------- barrier-free GEMM stage (MT m-tiles per warp) ----------------
template <int K16, int NT, int MT, int CHUNK>
__device__ __forceinline__ void gemm_stage(uint32_t wbase, float (*acc)[4],
                                           const uint32_t* aH, const uint32_t* bOff) {
    #pragma unroll
    for (int k = 0; k < K16; ++k) {
        uint32_t wb = wbase + k * CHUNK;
        uint32_t ah[MT][4];
        #pragma unroll
        for (int m = 0; m < MT; ++m) LDSM4(ah[m], aH[m] + k * XSTR);
        uint32_t b[2 * NT];
        if (NT == 9) {
            LDSM4(b, wb + bOff[0]); LDSM4(b + 4, wb + bOff[1]);
            LDSM4(b + 8, wb + bOff[2]); LDSM4(b + 12, wb + bOff[3]);
            LDSM2(b + 16, wb + bOff[4]);
        } else {
            LDSM4(b, wb + bOff[0]); LDSM4(b + 4, wb + bOff[1]);
        }
        #pragma unroll
        for (int j = 0; j < NT; ++j)
            #pragma unroll
            for (int m = 0; m < MT; ++m) mma_f16(acc[m * NT + j], ah[m], b + 2 * j);
    }
}

// ---------------- bulk weight loader ----------------
__device__ __forceinline__ void load_weights(uint32_t dst, const char* Wg, int bytes, int tid) {
    for (int off = tid * 16; off < bytes; off += 4096)
        CP16(dst + off, Wg + off);
    CP_COMMIT();
}

// ---------------- PW via tensor cores (1-pass fp16): g_PW = P·W1[128:256] + b1 ----------------
__global__ void __launch_bounds__(256, 2)
compute_pw_mma(const float* __restrict__ P, const float* __restrict__ b1) {
    const int s4 = blockIdx.x;
    const int nqh = blockIdx.y;
    extern __shared__ char smem[];
    uint32_t su = smem_u32(smem);
    const int tid = threadIdx.x;
    float* sB1 = (float*)(smem + PWK_B1);

    load_weights(su + PWK_W, (const char*)g_W1pw, WBYTES_A, tid);
    for (int i = tid; i < 144; i += 256) sB1[i] = (i < H_) ? b1[i] : 0.f;

    // X build: fp16 of P, float4 vectorized (128 rows)
    {
        int q = tid & 31, g = tid >> 5;
        int d0 = 4 * q, ks = d0 >> 4, kk = d0 & 15;
        char* xh = smem;
        #pragma unroll
        for (int b4 = 0; b4 < 4; ++b4) {
            int bb = g * 4 + b4;
            #pragma unroll
            for (int sl = 0; sl < 4; ++sl) {
                int s = s4 * 4 + sl;
                float4 pv = *(const float4*)&P[(bb * T_ + s) * D_ + d0];
                int row = sl * 32 + bb;
                int off = x_off(ks, row, kk);
                __half2 h01 = __floats2half2_rn(pv.x, pv.y);
                __half2 h23 = __floats2half2_rn(pv.z, pv.w);
                uint2 st; st.x = *(uint32_t*)&h01; st.y = *(uint32_t*)&h23;
                *(uint2*)(xh + off) = st;
            }
        }
    }
    CP_WAIT0();
    __syncthreads();

    const int wid = tid >> 5, lane = tid & 31;
    const int m0 = wid * 16;                 // 8 m-quads, 1 m-tile each
    const int grp = lane >> 2, c0 = 2 * (lane & 3);

    uint32_t aH0, bAB[5];
    {
        int l15 = lane & 15, chnk = lane >> 4;
        int row = m0 + l15;
        int phys = chnk ^ ((row >> 2) & 1);
        aH0 = su + row * 32 + phys * 16;
        int l7 = lane & 7, kh = (lane >> 3) & 1, pr = (lane >> 4) & 1;
        #pragma unroll
        for (int i = 0; i < 4; ++i)
            bAB[i] = (uint32_t)((nqh * 72 + 16 * i + pr * 8 + l7) * 48 + kh * 16);
        bAB[4] = (uint32_t)((nqh * 72 + 64 + l7) * 48 + kh * 16);
    }

    float acc[9][4];
    #pragma unroll
    for (int i = 0; i < 9; ++i) { acc[i][0] = acc[i][1] = acc[i][2] = acc[i][3] = 0.f; }
    gemm_stage<8, 9, 1, WCH_AB>(su + PWK_W, acc, &aH0, bAB);

    #pragma unroll
    for (int rp = 0; rp < 2; ++rp) {
        int row = m0 + grp + rp * 8;
        int sl = row >> 5, bb = row & 31;
        int s = s4 * 4 + sl;
        #pragma unroll
        for (int j = 0; j < 9; ++j) {
            int n0 = nqh * 72 + j * 8 + c0;
            float2 v;
            v.x = acc[j][rp * 2 + 0] + sB1[n0];
            v.y = acc[j][rp * 2 + 1] + sB1[n0 + 1];
            *(float2*)&g_PW[(s * BB_ + bb) * 144 + n0] = v;
        }
    }
}

// ---------------- relu epilogue: write fp16 X tile for next stage ----------------
__device__ __forceinline__ void epi_relu(char* smem, float (*acc)[4], const float* bias,
                                         int m0, int nbase, int lane) {
    char* xh = smem + OFF_X;
    const int grp = lane >> 2;
    const int c0 = 2 * (lane & 3);
    #pragma unroll
    for (int mt = 0; mt < 2; ++mt)
    #pragma unroll
    for (int j = 0; j < 9; ++j) {
        int n0 = nbase + j * 8 + c0;
        float bv0 = bias ? bias[n0] : 0.f;
        float bv1 = bias ? bias[n0 + 1] : 0.f;
        int ks = n0 >> 4, kk = n0 & 15;
        #pragma unroll
        for (int rp = 0; rp < 2; ++rp) {
            int row = m0 + mt * 64 + grp + rp * 8;
            float v0 = fmaxf(acc[mt * 9 + j][rp * 2 + 0] + bv0, 0.f);
            float v1 = fmaxf(acc[mt * 9 + j][rp * 2 + 1] + bv1, 0.f);
            __half2 hp; hp.x = __float2half(v0); hp.y = __float2half(v1);
            *(__half2*)(xh + x_off(ks, row, kk)) = hp;
        }
    }
}

// ---------------- main ----------------
__global__ void __launch_bounds__(256, 2)
mlp_main_kernel(const float* __restrict__ P,
                const float* __restrict__ b2, const float* __restrict__ b3,
                float* __restrict__ out) {
    const int mc = g_map[blockIdx.x];
    const int t = mc >> 8;
    const int c = mc & 255;
    const int s0 = t + 4 * c;

    extern __shared__ char smem[];
    uint32_t su = smem_u32(smem);
    const int tid = threadIdx.x;
    float* sB2 = (float*)(smem + OFF_B2);
    float* sB3 = (float*)(smem + OFF_B3);
    int* sRed = (int*)(smem + OFF_RED);    // inside W buffer, beyond stage-C weights

    load_weights(su + OFF_W, (const char*)g_W1h, WBYTES_A, tid);

    for (int i = tid; i < 144; i += 256) sB2[i] = (i < H_) ? b2[i] : 0.f;
    if (tid < 64) sB3[tid] = b3[tid];

    // feature build: float4 loads, 8B conflict-free stores (bank-rotated ksteps)
    {
        int q = tid & 31, g = tid >> 5;
        int d0 = 4 * q, ks = d0 >> 4, kk = d0 & 15;
        char* xh = smem + OFF_X;
        #pragma unroll
        for (int b4 = 0; b4 < 4; ++b4) {
            int bb = g * 4 + b4;
            float4 run4;
            if (c > 0) run4 = *(const float4*)&g_pre4[((t * 32 + (c - 1)) * BB_ + bb) * D_ + d0];
            else { run4.x = run4.y = run4.z = run4.w = -3.4e38f; }
            #pragma unroll
            for (int sl = 0; sl < 4; ++sl) {
                int s = s0 + sl;
                if (s < T_) {
                    float4 pv = *(const float4*)&P[(bb * T_ + s) * D_ + d0];
                    run4.x = fmaxf(run4.x, pv.x);
                    run4.y = fmaxf(run4.y, pv.y);
                    run4.z = fmaxf(run4.z, pv.z);
                    run4.w = fmaxf(run4.w, pv.w);
                }
                int row = sl * 32 + bb;
                int off = x_off(ks, row, kk);
                __half2 h01 = __floats2half2_rn(run4.x, run4.y);
                __half2 h23 = __floats2half2_rn(run4.z, run4.w);
                uint2 st; st.x = *(uint32_t*)&h01; st.y = *(uint32_t*)&h23;
                *(uint2*)(xh + off) = st;
            }
        }
    }

    const int wid = tid >> 5, lane = tid & 31;
    const int mq = wid >> 1, nq = wid & 1;      // 4 m-quads x 2 n-halves; m-tiles at m0, m0+64
    const int m0 = mq * 16;
    const int grp = lane >> 2, c0 = 2 * (lane & 3);

    float acc[18][4];

    // Stage A: acc preloaded from PW (P-part + b1) — BEFORE the wait, overlaps cp.async
    #pragma unroll
    for (int mt = 0; mt < 2; ++mt) {
        int r_lo = m0 + mt * 64 + grp, r_hi = r_lo + 8;
        int s_lo = min(s0 + (r_lo >> 5), T_ - 1), s_hi = min(s0 + (r_hi >> 5), T_ - 1);
        const float* pwlo = g_PW + (s_lo * BB_ + (r_lo & 31)) * 144;
        const float* pwhi = g_PW + (s_hi * BB_ + (r_hi & 31)) * 144;
        #pragma unroll
        for (int j = 0; j < 9; ++j) {
            int n0 = nq * 72 + j * 8 + c0;
            float2 vlo = *(const float2*)(pwlo + n0);
            float2 vhi = *(const float2*)(pwhi + n0);
            acc[mt * 9 + j][0] = vlo.x; acc[mt * 9 + j][1] = vlo.y;
            acc[mt * 9 + j][2] = vhi.x; acc[mt * 9 + j][3] = vhi.y;
        }
    }

    // per-lane ldmatrix addresses
    uint32_t aH[2], bAB[5], bC[2];
    {
        int l15 = lane & 15, chnk = lane >> 4;
        #pragma unroll
        for (int mt = 0; mt < 2; ++mt) {
            int row = m0 + mt * 64 + l15;
            int phys = chnk ^ ((row >> 2) & 1);
            aH[mt] = su + OFF_X + row * 32 + phys * 16;
        }
        int l7 = lane & 7, kh = (lane >> 3) & 1, pr = (lane >> 4) & 1;
        #pragma unroll
        for (int i = 0; i < 4; ++i)
            bAB[i] = (uint32_t)((nq * 72 + 16 * i + pr * 8 + l7) * 48 + kh * 16);
        bAB[4] = (uint32_t)((nq * 72 + 64 + l7) * 48 + kh * 16);
        #pragma unroll
        for (int i = 0; i < 2; ++i)
            bC[i] = (uint32_t)((nq * 32 + 16 * i + pr * 8 + l7) * 48 + kh * 16);
    }

    CP_WAIT0();
    __syncthreads();

    // Stage A: K=128 (8 ksteps), N=144
    gemm_stage<8, 9, 2, WCH_AB>(su + OFF_W, acc, aH, bAB);
    __syncthreads();
    load_weights(su + OFF_W, (const char*)g_W2h, WBYTES_B, tid);   // hide behind epi A
    epi_relu(smem, acc, (const float*)0, m0, nq * 72, lane);
    CP_WAIT0();
    __syncthreads();

    // Stage B: K=144 (9 ksteps), N=144
    #pragma unroll
    for (int i = 0; i < 18; ++i) { acc[i][0] = acc[i][1] = acc[i][2] = acc[i][3] = 0.f; }
    gemm_stage<9, 9, 2, WCH_AB>(su + OFF_W, acc, aH, bAB);
    __syncthreads();
    load_weights(su + OFF_W, (const char*)g_W3h, WBYTES_C, tid);   // hide behind epi B
    epi_relu(smem, acc, sB2, m0, nq * 72, lane);
    for (int i = tid; i < BB_ * O_; i += 256) sRed[i] = 0;   // init reduction buf (disjoint from C weights)
    CP_WAIT0();
    __syncthreads();

    // Stage C: K=144 (9 ksteps), N=64
    #pragma unroll
    for (int i = 0; i < 8; ++i) { acc[i][0] = acc[i][1] = acc[i][2] = acc[i][3] = 0.f; }
    gemm_stage<9, 4, 2, WCH_C>(su + OFF_W, acc, aH, bC);

    // final epilogue: max over m-tiles first (sigmoid monotonic), then smem atomics
    {
        #pragma unroll
        for (int rp = 0; rp < 2; ++rp) {
            int row0 = m0 + grp + rp * 8;          // mt=0
            int sl0 = row0 >> 5, sl1 = (row0 + 64) >> 5;
            int bb = row0 & 31;                    // same bb for both m-tiles
            bool ok0 = (s0 + sl0 < T_), ok1 = (s0 + sl1 < T_);
            if (ok0 | ok1) {
                #pragma unroll
                for (int j = 0; j < 4; ++j) {
                    int n0 = nq * 32 + j * 8 + c0;
                    float a0 = ok0 ? acc[j][rp * 2 + 0] : -3.4e38f;
                    float a1 = ok0 ? acc[j][rp * 2 + 1] : -3.4e38f;
                    if (ok1) {
                        a0 = fmaxf(a0, acc[4 + j][rp * 2 + 0]);
                        a1 = fmaxf(a1, acc[4 + j][rp * 2 + 1]);
                    }
                    float y0 = 1.f / (1.f + __expf(-5.f * (a0 + sB3[n0])));
                    float y1 = 1.f / (1.f + __expf(-5.f * (a1 + sB3[n0 + 1])));
                    atomicMax(&sRed[bb * O_ + n0], __float_as_int(y0));
                    atomicMax(&sRed[bb * O_ + n0 + 1], __float_as_int(y1));
                }
            }
        }
    }
    __syncthreads();
    for (int i = tid; i < BB_ * O_; i += 256) {
        int bb = i >> 6, o = i & 63;
        atomicMax((int*)(out + (bb * T_ + t) * O_ + o), sRed[i]);
    }
}

// ---------------- launch ----------------
extern "C" void kernel_launch(void* const* d_in, const int* in_sizes, int n_in,
                              void* d_out, int out_size) {
    const float* P  = (const float*)d_in[0];
    const float* W1 = (const float*)d_in[1];
    const float* b1 = (const float*)d_in[2];
    const float* W2 = (const float*)d_in[3];
    const float* b2 = (const float*)d_in[4];
    const float* W3 = (const float*)d_in[5];
    const float* b3 = (const float*)d_in[6];
    float* out = (float*)d_out;

    cudaFuncSetAttribute(mlp_main_kernel, cudaFuncAttributeMaxDynamicSharedMemorySize, SMEM_TOTAL);
    cudaFuncSetAttribute(compute_pw_mma, cudaFuncAttributeMaxDynamicSharedMemorySize, PWK_SMEM);

    prep_all<<<(4 * 32 * BB_ * D_) / 256, 256>>>(W1, W2, W3, P, out);
    pre_combine<<<(T_ * BB_ * D_) / 256, 256>>>();
    compute_pw_mma<<<dim3(32, 2), 256, PWK_SMEM>>>(P, b1);
    mlp_main_kernel<<<NBLK, 256, SMEM_TOTAL>>>(P, b2, b3, out);
}